// round 1
// baseline (speedup 1.0000x reference)
#include <cuda_runtime.h>
#include <math.h>

#define BB 4
#define NN 512
#define DD 1024
#define EE 8
#define HH 4096
#define RR 32            // candidate rows: (b in 0..3) x (n in 0..7)
#define OUT_ELEMS (BB*NN*DD)

// ---------------- device scratch (static globals; no allocs) ----------------
__device__ float g_wt[EE*DD];            // transposed gate weights [e][d]
__device__ int   g_flag[RR];             // flag[b*8+n]: expert n attained as argmax in batch b
__device__ float g_gate0[RR];            // softmax prob of e=0 for token (b, n<8)
__device__ float g_gs[RR];               // final gate scores
__device__ float g_hpart[8*RR*HH];       // stage1 split-K partials [split][r][h]
__device__ float g_h[RR*HH];             // gelu(h) [r][h]
__device__ float g_opart[16*RR*DD];      // stage2 split-K partials [split][r][d]

// ---------------- packed fp32x2 helpers (FFMA2 on sm_103a) ----------------
__device__ __forceinline__ void fma2(unsigned long long& d,
                                     unsigned long long a,
                                     unsigned long long b) {
    asm("fma.rn.f32x2 %0, %1, %2, %0;" : "+l"(d) : "l"(a), "l"(b));
}
__device__ __forceinline__ unsigned long long pack2(float lo, float hi) {
    unsigned long long r;
    asm("mov.b64 %0, {%1, %2};" : "=l"(r) : "f"(lo), "f"(hi));
    return r;
}
__device__ __forceinline__ void unpack2(unsigned long long v, float& lo, float& hi) {
    asm("mov.b64 {%0, %1}, %2;" : "=f"(lo), "=f"(hi) : "l"(v));
}

__device__ __forceinline__ int row_x_off(int r) {
    // candidate row r -> token (b = r>>3, n = r&7) -> x offset
    return ((r >> 3) * NN + (r & 7)) * DD;
}

// ---------------- kernel 1: init flags + transpose w_gate ----------------
__global__ void init_kernel(const float* __restrict__ w_gate) {
    int idx = blockIdx.x * blockDim.x + threadIdx.x;   // 8192 threads
    if (idx < EE * DD) {
        int e = idx & 7, d = idx >> 3;
        g_wt[e * DD + d] = w_gate[idx];                // w_gate[d*8+e] -> wt[e][d]
    }
    if (idx < RR) g_flag[idx] = 0;
}

// ---------------- kernel 2: gate logits, argmax, p(e=0) for n<8 ----------------
// 64 blocks x 256 threads; each warp handles 4 tokens (512 warps x 4 = 2048)
__global__ void gate_kernel(const float* __restrict__ x,
                            const float* __restrict__ b_gate) {
    int gw   = (blockIdx.x * blockDim.x + threadIdx.x) >> 5;
    int lane = threadIdx.x & 31;
    int tok0 = gw * 4;

    float acc[4][8];
#pragma unroll
    for (int k = 0; k < 4; k++)
#pragma unroll
        for (int e = 0; e < 8; e++) acc[k][e] = 0.f;

    const float* xp = x + (size_t)tok0 * DD + lane;
#pragma unroll 2
    for (int i = 0; i < 32; i++) {
        int d = i * 32 + lane;
        float xv0 = xp[0 * DD + i * 32];
        float xv1 = xp[1 * DD + i * 32];
        float xv2 = xp[2 * DD + i * 32];
        float xv3 = xp[3 * DD + i * 32];
#pragma unroll
        for (int e = 0; e < 8; e++) {
            float wv = g_wt[e * DD + d];
            acc[0][e] += xv0 * wv;
            acc[1][e] += xv1 * wv;
            acc[2][e] += xv2 * wv;
            acc[3][e] += xv3 * wv;
        }
    }
    // butterfly reduce all 32 accumulators across the warp
#pragma unroll
    for (int k = 0; k < 4; k++)
#pragma unroll
        for (int e = 0; e < 8; e++)
#pragma unroll
            for (int off = 16; off > 0; off >>= 1)
                acc[k][e] += __shfl_xor_sync(0xffffffffu, acc[k][e], off);

    if (lane < 4) {
        int tok = tok0 + lane;
        float l[8];
#pragma unroll
        for (int e = 0; e < 8; e++) l[e] = acc[lane][e] + b_gate[e];
        // first-occurrence argmax (matches jnp.argmax)
        int am = 0; float mx = l[0];
#pragma unroll
        for (int e = 1; e < 8; e++) if (l[e] > mx) { mx = l[e]; am = e; }
        int b = tok >> 9;          // tok / 512
        int n = tok & 511;
        g_flag[b * 8 + am] = 1;    // benign race: all writers store 1
        if (n < 8) {
            float s = 0.f, p0 = 0.f;
#pragma unroll
            for (int e = 0; e < 8; e++) {
                float t = expf(l[e] - mx);
                s += t;
                if (e == 0) p0 = t;
            }
            g_gate0[b * 8 + n] = p0 / s;
        }
    }
}

// ---------------- kernel 3: gate scores + aux loss (1 warp) ----------------
__global__ void score_loss_kernel(float* __restrict__ out) {
    int i = threadIdx.x;                 // 32 threads: b = i>>3, n = i&7
    float m = g_flag[i] ? g_gate0[i] : 0.f;
    float s = m;                         // sum over b (lanes sharing n)
    s += __shfl_xor_sync(0xffffffffu, s, 8);
    s += __shfl_xor_sync(0xffffffffu, s, 16);
    float gs = m / (s + 1e-6f) * 4.0f;   // capacity = float(int(1.0*B)) = 4
    g_gs[i] = gs;

    float imp = gs;
    imp += __shfl_xor_sync(0xffffffffu, imp, 8);
    imp += __shfl_xor_sync(0xffffffffu, imp, 16);
    float ld = (float)g_flag[i];
    ld += __shfl_xor_sync(0xffffffffu, ld, 8);
    ld += __shfl_xor_sync(0xffffffffu, ld, 16);

    float s1 = (i < 8) ? imp       : 0.f;
    float s2 = (i < 8) ? imp * imp : 0.f;
    float s3 = (i < 8) ? ld        : 0.f;
    float s4 = (i < 8) ? ld * ld   : 0.f;
#pragma unroll
    for (int off = 16; off > 0; off >>= 1) {
        s1 += __shfl_xor_sync(0xffffffffu, s1, off);
        s2 += __shfl_xor_sync(0xffffffffu, s2, off);
        s3 += __shfl_xor_sync(0xffffffffu, s3, off);
        s4 += __shfl_xor_sync(0xffffffffu, s4, off);
    }
    if (i == 0) {
        const float NEL = (float)(NN * EE);          // 4096 elements in [N,E]
        float m1 = s1 / NEL;
        float v1 = (s2 - s1 * s1 / NEL) / (NEL - 1.f);   // ddof=1
        float m2 = s3 / NEL;
        float v2 = (s4 - s3 * s3 / NEL) / (NEL - 1.f);
        out[OUT_ELEMS] = v1 / (m1 * m1 + 1e-10f) + v2 / (m2 * m2 + 1e-10f);
    }
}

// ---------------- kernel 4: stage1 GEMM  h_pre = x[32,1024] @ w1[0]  ----------------
// grid (32 j-tiles of 128, 8 d-splits of 128), 128 threads (4 warps).
// Warp w owns rows 8w..8w+7 as 4 fp32x2 pairs; lane owns 4 h-columns.
__global__ void stage1_kernel(const float* __restrict__ x,
                              const float* __restrict__ w1) {
    __shared__ float2 xs2[16][128];      // [row-pair][d]  (16 KB)
    int t = threadIdx.x;
    int jt = blockIdx.x, ds = blockIdx.y;
    int dbase = ds * 128;

#pragma unroll
    for (int p = 0; p < 16; p++) {
        xs2[p][t] = make_float2(x[row_x_off(2 * p)     + dbase + t],
                                x[row_x_off(2 * p + 1) + dbase + t]);
    }
    __syncthreads();

    int lane = t & 31, w = t >> 5;
    unsigned long long acc[4][4];
#pragma unroll
    for (int p = 0; p < 4; p++)
#pragma unroll
        for (int m = 0; m < 4; m++) acc[p][m] = 0ULL;

    const float* wbase = w1 + (size_t)dbase * HH + jt * 128 + lane;
#pragma unroll 4
    for (int d = 0; d < 128; d++) {
        const float* wr = wbase + (size_t)d * HH;
        unsigned long long wp0 = pack2(wr[0],  wr[0]);
        unsigned long long wp1 = pack2(wr[32], wr[32]);
        unsigned long long wp2 = pack2(wr[64], wr[64]);
        unsigned long long wp3 = pack2(wr[96], wr[96]);
#pragma unroll
        for (int pl = 0; pl < 4; pl++) {
            unsigned long long xp =
                *reinterpret_cast<const unsigned long long*>(&xs2[w * 4 + pl][d]);
            fma2(acc[pl][0], xp, wp0);
            fma2(acc[pl][1], xp, wp1);
            fma2(acc[pl][2], xp, wp2);
            fma2(acc[pl][3], xp, wp3);
        }
    }
#pragma unroll
    for (int pl = 0; pl < 4; pl++)
#pragma unroll
        for (int m = 0; m < 4; m++) {
            float lo, hi; unpack2(acc[pl][m], lo, hi);
            int r0 = w * 8 + pl * 2;
            int h  = jt * 128 + lane + 32 * m;
            g_hpart[((size_t)ds * RR + r0)     * HH + h] = lo;
            g_hpart[((size_t)ds * RR + r0 + 1) * HH + h] = hi;
        }
}

// ---------------- kernel 5: split-K reduce + bias + exact GELU ----------------
__global__ void gelu_kernel(const float* __restrict__ b1) {
    int idx = blockIdx.x * blockDim.x + threadIdx.x;    // 32768 threads x 4
#pragma unroll
    for (int q = 0; q < 4; q++) {
        int id = idx + q * 32768;
        int r = id >> 12, h = id & 4095;
        float v = b1[h];
#pragma unroll
        for (int s = 0; s < 8; s++) v += g_hpart[((size_t)s * RR + r) * HH + h];
        g_h[id] = 0.5f * v * (1.0f + erff(v * 0.70710678118654752440f));
    }
}

// ---------------- kernel 6: stage2 GEMM  o_pre = h[32,4096] @ w2[0] ----------------
// grid (8 d-tiles of 128, 16 j-splits of 256), 128 threads.
__global__ void stage2_kernel(const float* __restrict__ w2) {
    __shared__ float2 hs2[16][256];      // 32 KB
    int t = threadIdx.x;
    int dt = blockIdx.x, js = blockIdx.y;
    int jbase = js * 256;

#pragma unroll
    for (int p = 0; p < 16; p++) {
        hs2[p][t]       = make_float2(g_h[(2 * p) * HH + jbase + t],
                                      g_h[(2 * p + 1) * HH + jbase + t]);
        hs2[p][t + 128] = make_float2(g_h[(2 * p) * HH + jbase + t + 128],
                                      g_h[(2 * p + 1) * HH + jbase + t + 128]);
    }
    __syncthreads();

    int lane = t & 31, w = t >> 5;
    unsigned long long acc[4][4];
#pragma unroll
    for (int p = 0; p < 4; p++)
#pragma unroll
        for (int m = 0; m < 4; m++) acc[p][m] = 0ULL;

    const float* wbase = w2 + (size_t)jbase * DD + dt * 128 + lane;
#pragma unroll 4
    for (int j = 0; j < 256; j++) {
        const float* wr = wbase + (size_t)j * DD;
        unsigned long long wp0 = pack2(wr[0],  wr[0]);
        unsigned long long wp1 = pack2(wr[32], wr[32]);
        unsigned long long wp2 = pack2(wr[64], wr[64]);
        unsigned long long wp3 = pack2(wr[96], wr[96]);
#pragma unroll
        for (int pl = 0; pl < 4; pl++) {
            unsigned long long hp =
                *reinterpret_cast<const unsigned long long*>(&hs2[w * 4 + pl][j]);
            fma2(acc[pl][0], hp, wp0);
            fma2(acc[pl][1], hp, wp1);
            fma2(acc[pl][2], hp, wp2);
            fma2(acc[pl][3], hp, wp3);
        }
    }
#pragma unroll
    for (int pl = 0; pl < 4; pl++)
#pragma unroll
        for (int m = 0; m < 4; m++) {
            float lo, hi; unpack2(acc[pl][m], lo, hi);
            int r0 = w * 8 + pl * 2;
            int d  = dt * 128 + lane + 32 * m;
            g_opart[((size_t)js * RR + r0)     * DD + d] = lo;
            g_opart[((size_t)js * RR + r0 + 1) * DD + d] = hi;
        }
}

// ---------------- kernel 7: reduce partials, add b2, scale by gate, write out ----------------
__global__ void final_kernel(const float* __restrict__ b2,
                             float* __restrict__ out) {
    int r = blockIdx.x;                  // one block per candidate row
    float gs = g_gs[r];
    int off = row_x_off(r);
#pragma unroll
    for (int k = 0; k < 4; k++) {
        int d = threadIdx.x + 256 * k;
        float v = b2[d];
#pragma unroll
        for (int s = 0; s < 16; s++) v += g_opart[((size_t)s * RR + r) * DD + d];
        out[off + d] = gs * v;
    }
}

// ---------------- launch ----------------
extern "C" void kernel_launch(void* const* d_in, const int* in_sizes, int n_in,
                              void* d_out, int out_size) {
    const float* x      = (const float*)d_in[0];
    const float* w_gate = (const float*)d_in[1];
    const float* b_gate = (const float*)d_in[2];
    const float* w1     = (const float*)d_in[3];   // [E,D,H]; expert 0 slice used
    const float* b1     = (const float*)d_in[4];   // [E,H]
    const float* w2     = (const float*)d_in[5];   // [E,H,D]
    const float* b2     = (const float*)d_in[6];   // [E,D]
    float* out = (float*)d_out;

    // out[:B*N*D] = 0; active rows overwritten below; loss written by score_loss.
    cudaMemsetAsync(d_out, 0, (size_t)OUT_ELEMS * sizeof(float));

    init_kernel<<<32, 256>>>(w_gate);
    gate_kernel<<<64, 256>>>(x, b_gate);
    score_loss_kernel<<<1, 32>>>(out);
    stage1_kernel<<<dim3(32, 8), 128>>>(x, w1);
    gelu_kernel<<<128, 256>>>(b1);
    stage2_kernel<<<dim3(8, 16), 128>>>(w2);
    final_kernel<<<32, 256>>>(b2, out);
}

// round 5
// speedup vs baseline: 2.7026x; 2.7026x over previous
#include <cuda_runtime.h>
#include <math.h>

#define BB 4
#define NN 512
#define DD 1024
#define EE 8
#define HH 4096
#define RR 32            // candidate rows: (b in 0..3) x (n in 0..7)
#define OUT_ELEMS (BB*NN*DD)

#define S1_SPLITS 16     // stage1 d-splits (64 d each)
#define S2_SPLITS 64     // stage2 j-splits (64 j each)

// ---------------- device scratch ----------------
__device__ float g_wt[EE*DD];                // transposed gate weights [e][d]
__device__ int   g_flag[RR];
__device__ float g_gate0[RR];
__device__ float g_gs[RR];
__device__ float g_hpart[S1_SPLITS*RR*HH];   // 8 MB
__device__ float g_h[RR*HH];
__device__ float g_opart[S2_SPLITS*RR*DD];   // 8 MB

// ---------------- packed fp32x2 helpers ----------------
__device__ __forceinline__ void fma2(unsigned long long& d,
                                     unsigned long long a,
                                     unsigned long long b) {
    asm("fma.rn.f32x2 %0, %1, %2, %0;" : "+l"(d) : "l"(a), "l"(b));
}
__device__ __forceinline__ unsigned long long pack2(float lo, float hi) {
    unsigned long long r;
    asm("mov.b64 %0, {%1, %2};" : "=l"(r) : "f"(lo), "f"(hi));
    return r;
}
__device__ __forceinline__ void unpack2(unsigned long long v, float& lo, float& hi) {
    asm("mov.b64 {%0, %1}, %2;" : "=f"(lo), "=f"(hi) : "l"(v));
}

__device__ __forceinline__ int row_x_off(int r) {
    return ((r >> 3) * NN + (r & 7)) * DD;
}

// ---------------- kernel 1: init flags + transpose w_gate ----------------
__global__ void init_kernel(const float* __restrict__ w_gate) {
    int idx = blockIdx.x * blockDim.x + threadIdx.x;
    if (idx < EE * DD) {
        int e = idx & 7, d = idx >> 3;
        g_wt[e * DD + d] = w_gate[idx];
    }
    if (idx < RR) g_flag[idx] = 0;
}

// ---------------- kernel 2: gate logits, argmax, p(e=0) for n<8 ----------------
// 256 blocks x 256 threads; one token per warp (2048 warps)
__global__ void gate_kernel(const float* __restrict__ x,
                            const float* __restrict__ b_gate) {
    int tok  = (blockIdx.x * blockDim.x + threadIdx.x) >> 5;
    int lane = threadIdx.x & 31;

    float acc[8];
#pragma unroll
    for (int e = 0; e < 8; e++) acc[e] = 0.f;

    const float* xp = x + (size_t)tok * DD + lane;
#pragma unroll 4
    for (int i = 0; i < 32; i++) {
        int d = i * 32 + lane;
        float xv = xp[i * 32];
#pragma unroll
        for (int e = 0; e < 8; e++) acc[e] += xv * g_wt[e * DD + d];
    }
#pragma unroll
    for (int e = 0; e < 8; e++)
#pragma unroll
        for (int off = 16; off > 0; off >>= 1)
            acc[e] += __shfl_xor_sync(0xffffffffu, acc[e], off);

    if (lane == 0) {
        float l[8];
#pragma unroll
        for (int e = 0; e < 8; e++) l[e] = acc[e] + b_gate[e];
        int am = 0; float mx = l[0];
#pragma unroll
        for (int e = 1; e < 8; e++) if (l[e] > mx) { mx = l[e]; am = e; }
        int b = tok >> 9;
        int n = tok & 511;
        g_flag[b * 8 + am] = 1;          // benign race: writers all store 1
        if (n < 8) {
            float s = 0.f, p0 = 0.f;
#pragma unroll
            for (int e = 0; e < 8; e++) {
                float t = expf(l[e] - mx);
                s += t;
                if (e == 0) p0 = t;
            }
            g_gate0[b * 8 + n] = p0 / s;
        }
    }
}

// ---------------- kernel 3: gate scores + aux loss (1 warp) ----------------
__global__ void score_loss_kernel(float* __restrict__ out) {
    int i = threadIdx.x;                 // b = i>>3, n = i&7
    float m = g_flag[i] ? g_gate0[i] : 0.f;
    float s = m;
    s += __shfl_xor_sync(0xffffffffu, s, 8);
    s += __shfl_xor_sync(0xffffffffu, s, 16);
    float gs = m / (s + 1e-6f) * 4.0f;   // capacity = 4
    g_gs[i] = gs;

    float imp = gs;
    imp += __shfl_xor_sync(0xffffffffu, imp, 8);
    imp += __shfl_xor_sync(0xffffffffu, imp, 16);
    float ld = (float)g_flag[i];
    ld += __shfl_xor_sync(0xffffffffu, ld, 8);
    ld += __shfl_xor_sync(0xffffffffu, ld, 16);

    float s1 = (i < 8) ? imp       : 0.f;
    float s2 = (i < 8) ? imp * imp : 0.f;
    float s3 = (i < 8) ? ld        : 0.f;
    float s4 = (i < 8) ? ld * ld   : 0.f;
#pragma unroll
    for (int off = 16; off > 0; off >>= 1) {
        s1 += __shfl_xor_sync(0xffffffffu, s1, off);
        s2 += __shfl_xor_sync(0xffffffffu, s2, off);
        s3 += __shfl_xor_sync(0xffffffffu, s3, off);
        s4 += __shfl_xor_sync(0xffffffffu, s4, off);
    }
    if (i == 0) {
        const float NEL = (float)(NN * EE);
        float m1 = s1 / NEL;
        float v1 = (s2 - s1 * s1 / NEL) / (NEL - 1.f);
        float m2 = s3 / NEL;
        float v2 = (s4 - s3 * s3 / NEL) / (NEL - 1.f);
        out[OUT_ELEMS] = v1 / (m1 * m1 + 1e-10f) + v2 / (m2 * m2 + 1e-10f);
    }
}

// ---------------- kernel 4: stage1 GEMM  h_pre = x[32,1024] @ w1[0] ----------------
// grid (32 j-tiles of 128 cols, 16 d-splits of 64), 128 threads (4 warps).
// Thread: 4 consecutive cols (lane*4, LDG.128 weights) x 8 rows (warp-split).
__global__ void stage1_kernel(const float* __restrict__ x,
                              const float* __restrict__ w1) {
    __shared__ float2 xs2[16][64];       // [row-pair][d] 8 KB
    int t = threadIdx.x;
    int jb = blockIdx.x * 128;
    int db = blockIdx.y * 64;

#pragma unroll
    for (int q = 0; q < 8; q++) {
        int idx = t + 128 * q;           // 1024 entries
        int p = idx >> 6, dd = idx & 63;
        xs2[p][dd] = make_float2(x[row_x_off(2 * p)     + db + dd],
                                 x[row_x_off(2 * p + 1) + db + dd]);
    }
    __syncthreads();

    int lane = t & 31, w = t >> 5;
    unsigned long long acc[4][4];        // [row-pair][col]
#pragma unroll
    for (int p = 0; p < 4; p++)
#pragma unroll
        for (int c = 0; c < 4; c++) acc[p][c] = 0ULL;

    const float* wbase = w1 + (size_t)db * HH + jb + lane * 4;
#pragma unroll 4
    for (int d = 0; d < 64; d++) {
        float4 wv = *reinterpret_cast<const float4*>(wbase + (size_t)d * HH);
        unsigned long long wp0 = pack2(wv.x, wv.x);
        unsigned long long wp1 = pack2(wv.y, wv.y);
        unsigned long long wp2 = pack2(wv.z, wv.z);
        unsigned long long wp3 = pack2(wv.w, wv.w);
#pragma unroll
        for (int pl = 0; pl < 4; pl++) {
            unsigned long long xp =
                *reinterpret_cast<const unsigned long long*>(&xs2[w * 4 + pl][d]);
            fma2(acc[pl][0], xp, wp0);
            fma2(acc[pl][1], xp, wp1);
            fma2(acc[pl][2], xp, wp2);
            fma2(acc[pl][3], xp, wp3);
        }
    }
    // repack so each row writes one float4 (coalesced 512B/warp store)
#pragma unroll
    for (int pl = 0; pl < 4; pl++) {
        float4 v0, v1;
        unpack2(acc[pl][0], v0.x, v1.x);
        unpack2(acc[pl][1], v0.y, v1.y);
        unpack2(acc[pl][2], v0.z, v1.z);
        unpack2(acc[pl][3], v0.w, v1.w);
        int r0 = w * 8 + pl * 2;
        size_t base = ((size_t)blockIdx.y * RR + r0) * HH + jb + lane * 4;
        *reinterpret_cast<float4*>(&g_hpart[base])      = v0;
        *reinterpret_cast<float4*>(&g_hpart[base + HH]) = v1;
    }
}

// ---------------- kernel 5: split-K reduce + bias + exact GELU ----------------
__global__ void gelu_kernel(const float* __restrict__ b1) {
    int idx = blockIdx.x * blockDim.x + threadIdx.x;    // 32768 threads x 4
#pragma unroll
    for (int q = 0; q < 4; q++) {
        int id = idx + q * 32768;
        int h = id & 4095;
        float v = b1[h];
#pragma unroll
        for (int s = 0; s < S1_SPLITS; s++) v += g_hpart[(size_t)s * (RR * HH) + id];
        g_h[id] = 0.5f * v * (1.0f + erff(v * 0.70710678118654752440f));
    }
}

// ---------------- kernel 6: stage2 GEMM  o_pre = h[32,4096] @ w2[0] ----------------
// grid (8 d-tiles of 128 cols, 64 j-splits of 64), 128 threads (4 warps).
__global__ void stage2_kernel(const float* __restrict__ w2) {
    __shared__ float2 hs2[16][64];       // 8 KB
    int t = threadIdx.x;
    int dbt = blockIdx.x * 128;
    int jb  = blockIdx.y * 64;

#pragma unroll
    for (int q = 0; q < 8; q++) {
        int idx = t + 128 * q;
        int p = idx >> 6, jj = idx & 63;
        hs2[p][jj] = make_float2(g_h[(2 * p)     * HH + jb + jj],
                                 g_h[(2 * p + 1) * HH + jb + jj]);
    }
    __syncthreads();

    int lane = t & 31, w = t >> 5;
    unsigned long long acc[4][4];
#pragma unroll
    for (int p = 0; p < 4; p++)
#pragma unroll
        for (int c = 0; c < 4; c++) acc[p][c] = 0ULL;

    const float* wbase = w2 + (size_t)jb * DD + dbt + lane * 4;
#pragma unroll 4
    for (int j = 0; j < 64; j++) {
        float4 wv = *reinterpret_cast<const float4*>(wbase + (size_t)j * DD);
        unsigned long long wp0 = pack2(wv.x, wv.x);
        unsigned long long wp1 = pack2(wv.y, wv.y);
        unsigned long long wp2 = pack2(wv.z, wv.z);
        unsigned long long wp3 = pack2(wv.w, wv.w);
#pragma unroll
        for (int pl = 0; pl < 4; pl++) {
            unsigned long long hp =
                *reinterpret_cast<const unsigned long long*>(&hs2[w * 4 + pl][j]);
            fma2(acc[pl][0], hp, wp0);
            fma2(acc[pl][1], hp, wp1);
            fma2(acc[pl][2], hp, wp2);
            fma2(acc[pl][3], hp, wp3);
        }
    }
#pragma unroll
    for (int pl = 0; pl < 4; pl++) {
        float4 v0, v1;
        unpack2(acc[pl][0], v0.x, v1.x);
        unpack2(acc[pl][1], v0.y, v1.y);
        unpack2(acc[pl][2], v0.z, v1.z);
        unpack2(acc[pl][3], v0.w, v1.w);
        int r0 = w * 8 + pl * 2;
        size_t base = ((size_t)blockIdx.y * RR + r0) * DD + dbt + lane * 4;
        *reinterpret_cast<float4*>(&g_opart[base])      = v0;
        *reinterpret_cast<float4*>(&g_opart[base + DD]) = v1;
    }
}

// ---------------- kernel 7: reduce partials, add b2, scale by gate, write ----------------
// grid (32 rows, 4 col-chunks), 256 threads
__global__ void final_kernel(const float* __restrict__ b2,
                             float* __restrict__ out) {
    int r = blockIdx.x;
    int d = blockIdx.y * 256 + threadIdx.x;
    float gs = g_gs[r];
    float v = b2[d];
#pragma unroll
    for (int s = 0; s < S2_SPLITS; s++) v += g_opart[((size_t)s * RR + r) * DD + d];
    out[row_x_off(r) + d] = gs * v;
}

// ---------------- launch ----------------
extern "C" void kernel_launch(void* const* d_in, const int* in_sizes, int n_in,
                              void* d_out, int out_size) {
    const float* x      = (const float*)d_in[0];
    const float* w_gate = (const float*)d_in[1];
    const float* b_gate = (const float*)d_in[2];
    const float* w1     = (const float*)d_in[3];
    const float* b1     = (const float*)d_in[4];
    const float* w2     = (const float*)d_in[5];
    const float* b2     = (const float*)d_in[6];
    float* out = (float*)d_out;

    cudaMemsetAsync(d_out, 0, (size_t)OUT_ELEMS * sizeof(float));

    init_kernel<<<32, 256>>>(w_gate);
    gate_kernel<<<256, 256>>>(x, b_gate);
    score_loss_kernel<<<1, 32>>>(out);
    stage1_kernel<<<dim3(32, S1_SPLITS), 128>>>(x, w1);
    gelu_kernel<<<128, 256>>>(b1);
    stage2_kernel<<<dim3(8, S2_SPLITS), 128>>>(w2);
    final_kernel<<<dim3(32, 4), 256>>>(b2, out);
}

// round 6
// speedup vs baseline: 2.7800x; 1.0286x over previous
#include <cuda_runtime.h>
#include <math.h>

#define BB 4
#define NN 512
#define DD 1024
#define EE 8
#define HH 4096
#define RR 32            // candidate rows: (b in 0..3) x (n in 0..7)
#define OUT_ELEMS (BB*NN*DD)

#define S1_SPLITS 16     // stage1 d-splits (64 d each)
#define S2_SPLITS 64     // stage2 j-splits (64 j each)

// ---------------- device scratch ----------------
__device__ float g_wt[EE*DD];                // transposed gate weights [e][d]
__device__ int   g_flag[RR];
__device__ float g_gate0[RR];
__device__ float g_gs[RR];
__device__ float g_hpart[S1_SPLITS*RR*HH];   // 8 MB
__device__ float g_h[RR*HH];
__device__ float g_opart[S2_SPLITS*RR*DD];   // 8 MB

// ---------------- packed fp32x2 helpers ----------------
__device__ __forceinline__ void fma2(unsigned long long& d,
                                     unsigned long long a,
                                     unsigned long long b) {
    asm("fma.rn.f32x2 %0, %1, %2, %0;" : "+l"(d) : "l"(a), "l"(b));
}
__device__ __forceinline__ unsigned long long pack2(float lo, float hi) {
    unsigned long long r;
    asm("mov.b64 %0, {%1, %2};" : "=l"(r) : "f"(lo), "f"(hi));
    return r;
}
__device__ __forceinline__ void unpack2(unsigned long long v, float& lo, float& hi) {
    asm("mov.b64 {%0, %1}, %2;" : "=f"(lo), "=f"(hi) : "l"(v));
}

__device__ __forceinline__ int row_x_off(int r) {
    return ((r >> 3) * NN + (r & 7)) * DD;
}

// ---------------- kernel 1: init flags + transpose w_gate ----------------
__global__ void init_kernel(const float* __restrict__ w_gate) {
    int idx = blockIdx.x * blockDim.x + threadIdx.x;
    if (idx < EE * DD) {
        int e = idx & 7, d = idx >> 3;
        g_wt[e * DD + d] = w_gate[idx];
    }
    if (idx < RR) g_flag[idx] = 0;
}

// ---------------- kernel 2: gate logits, argmax, p(e=0) for n<8 ----------------
// 256 blocks x 256 threads; one token per warp; float4 loads (8 iters)
__global__ void gate_kernel(const float* __restrict__ x,
                            const float* __restrict__ b_gate) {
    int tok  = (blockIdx.x * blockDim.x + threadIdx.x) >> 5;
    int lane = threadIdx.x & 31;

    float acc[8];
#pragma unroll
    for (int e = 0; e < 8; e++) acc[e] = 0.f;

    const float4* xp = reinterpret_cast<const float4*>(x + (size_t)tok * DD) + lane;
#pragma unroll
    for (int i = 0; i < 8; i++) {
        int d4 = i * 32 + lane;                 // float4 index; d = d4*4
        float4 xv = xp[i * 32];
#pragma unroll
        for (int e = 0; e < 8; e++) {
            float4 wv = *reinterpret_cast<const float4*>(&g_wt[e * DD + d4 * 4]);
            acc[e] += xv.x * wv.x + xv.y * wv.y + xv.z * wv.z + xv.w * wv.w;
        }
    }
#pragma unroll
    for (int e = 0; e < 8; e++)
#pragma unroll
        for (int off = 16; off > 0; off >>= 1)
            acc[e] += __shfl_xor_sync(0xffffffffu, acc[e], off);

    if (lane == 0) {
        float l[8];
#pragma unroll
        for (int e = 0; e < 8; e++) l[e] = acc[e] + b_gate[e];
        int am = 0; float mx = l[0];
#pragma unroll
        for (int e = 1; e < 8; e++) if (l[e] > mx) { mx = l[e]; am = e; }
        int b = tok >> 9;
        int n = tok & 511;
        g_flag[b * 8 + am] = 1;          // benign race: writers all store 1
        if (n < 8) {
            float s = 0.f, p0 = 0.f;
#pragma unroll
            for (int e = 0; e < 8; e++) {
                float t = expf(l[e] - mx);
                s += t;
                if (e == 0) p0 = t;
            }
            g_gate0[b * 8 + n] = p0 / s;
        }
    }
}

// ---------------- kernel 3: gate scores + aux loss (1 warp) ----------------
__global__ void score_loss_kernel(float* __restrict__ out) {
    int i = threadIdx.x;                 // b = i>>3, n = i&7
    float m = g_flag[i] ? g_gate0[i] : 0.f;
    float s = m;
    s += __shfl_xor_sync(0xffffffffu, s, 8);
    s += __shfl_xor_sync(0xffffffffu, s, 16);
    float gs = m / (s + 1e-6f) * 4.0f;   // capacity = 4
    g_gs[i] = gs;

    float imp = gs;
    imp += __shfl_xor_sync(0xffffffffu, imp, 8);
    imp += __shfl_xor_sync(0xffffffffu, imp, 16);
    float ld = (float)g_flag[i];
    ld += __shfl_xor_sync(0xffffffffu, ld, 8);
    ld += __shfl_xor_sync(0xffffffffu, ld, 16);

    float s1 = (i < 8) ? imp       : 0.f;
    float s2 = (i < 8) ? imp * imp : 0.f;
    float s3 = (i < 8) ? ld        : 0.f;
    float s4 = (i < 8) ? ld * ld   : 0.f;
#pragma unroll
    for (int off = 16; off > 0; off >>= 1) {
        s1 += __shfl_xor_sync(0xffffffffu, s1, off);
        s2 += __shfl_xor_sync(0xffffffffu, s2, off);
        s3 += __shfl_xor_sync(0xffffffffu, s3, off);
        s4 += __shfl_xor_sync(0xffffffffu, s4, off);
    }
    if (i == 0) {
        const float NEL = (float)(NN * EE);
        float m1 = s1 / NEL;
        float v1 = (s2 - s1 * s1 / NEL) / (NEL - 1.f);
        float m2 = s3 / NEL;
        float v2 = (s4 - s3 * s3 / NEL) / (NEL - 1.f);
        out[OUT_ELEMS] = v1 / (m1 * m1 + 1e-10f) + v2 / (m2 * m2 + 1e-10f);
    }
}

// ---------------- kernel 4: stage1 GEMM  h_pre = x[32,1024] @ w1[0] ----------------
// grid (32 j-tiles of 128 cols, 16 d-splits of 64), 256 threads (8 warps).
// Warp w owns rows 4w..4w+3. f32x2 pairs COLUMNS: w LDG.128 -> two aligned reg
// pairs, x pre-splatted in smem -> LDS.64 gives (x,x). Zero pack MOVs in loop.
__global__ void stage1_kernel(const float* __restrict__ x,
                              const float* __restrict__ w1) {
    __shared__ float2 xs[RR][64];        // splatted x tile, 16 KB
    int t = threadIdx.x;
    int jb = blockIdx.x * 128;
    int db = blockIdx.y * 64;

#pragma unroll
    for (int q = 0; q < 8; q++) {
        int idx = t + 256 * q;           // 2048 entries
        int row = idx >> 6, dd = idx & 63;
        float v = x[row_x_off(row) + db + dd];
        xs[row][dd] = make_float2(v, v);
    }
    __syncthreads();

    int lane = t & 31, w = t >> 5;
    unsigned long long acc[4][2];        // [row][colpair]
#pragma unroll
    for (int r = 0; r < 4; r++) { acc[r][0] = 0ULL; acc[r][1] = 0ULL; }

    const float* wbase = w1 + (size_t)db * HH + jb + lane * 4;
#pragma unroll 8
    for (int d = 0; d < 64; d++) {
        float4 wv = *reinterpret_cast<const float4*>(wbase + (size_t)d * HH);
        unsigned long long wp01 = pack2(wv.x, wv.y);
        unsigned long long wp23 = pack2(wv.z, wv.w);
#pragma unroll
        for (int r = 0; r < 4; r++) {
            unsigned long long xp =
                *reinterpret_cast<const unsigned long long*>(&xs[w * 4 + r][d]);
            fma2(acc[r][0], xp, wp01);
            fma2(acc[r][1], xp, wp23);
        }
    }
#pragma unroll
    for (int r = 0; r < 4; r++) {
        float4 o;
        unpack2(acc[r][0], o.x, o.y);
        unpack2(acc[r][1], o.z, o.w);
        size_t base = ((size_t)blockIdx.y * RR + (w * 4 + r)) * HH + jb + lane * 4;
        *reinterpret_cast<float4*>(&g_hpart[base]) = o;
    }
}

// ---------------- kernel 5: split-K reduce + bias + exact GELU (float4) ----------------
// 128 blocks x 256 threads, one float4 each (32K float4 = 128K floats)
__global__ void gelu_kernel(const float* __restrict__ b1) {
    int f4 = blockIdx.x * blockDim.x + threadIdx.x;     // 0..32767
    int h = (f4 * 4) & 4095;
    float4 v = *reinterpret_cast<const float4*>(&b1[h]);
#pragma unroll
    for (int s = 0; s < S1_SPLITS; s++) {
        float4 p = *reinterpret_cast<const float4*>(&g_hpart[(size_t)s * (RR * HH) + f4 * 4]);
        v.x += p.x; v.y += p.y; v.z += p.z; v.w += p.w;
    }
    const float k = 0.70710678118654752440f;
    v.x = 0.5f * v.x * (1.0f + erff(v.x * k));
    v.y = 0.5f * v.y * (1.0f + erff(v.y * k));
    v.z = 0.5f * v.z * (1.0f + erff(v.z * k));
    v.w = 0.5f * v.w * (1.0f + erff(v.w * k));
    *reinterpret_cast<float4*>(&g_h[f4 * 4]) = v;
}

// ---------------- kernel 6: stage2 GEMM  o_pre = h[32,4096] @ w2[0] ----------------
// grid (8 d-tiles of 128 cols, 64 j-splits of 64), 256 threads (8 warps).
__global__ void stage2_kernel(const float* __restrict__ w2) {
    __shared__ float2 hs[RR][64];        // splatted h tile, 16 KB
    int t = threadIdx.x;
    int dbt = blockIdx.x * 128;
    int jb  = blockIdx.y * 64;

#pragma unroll
    for (int q = 0; q < 8; q++) {
        int idx = t + 256 * q;
        int row = idx >> 6, jj = idx & 63;
        float v = g_h[row * HH + jb + jj];
        hs[row][jj] = make_float2(v, v);
    }
    __syncthreads();

    int lane = t & 31, w = t >> 5;
    unsigned long long acc[4][2];
#pragma unroll
    for (int r = 0; r < 4; r++) { acc[r][0] = 0ULL; acc[r][1] = 0ULL; }

    const float* wbase = w2 + (size_t)jb * DD + dbt + lane * 4;
#pragma unroll 8
    for (int j = 0; j < 64; j++) {
        float4 wv = *reinterpret_cast<const float4*>(wbase + (size_t)j * DD);
        unsigned long long wp01 = pack2(wv.x, wv.y);
        unsigned long long wp23 = pack2(wv.z, wv.w);
#pragma unroll
        for (int r = 0; r < 4; r++) {
            unsigned long long hp =
                *reinterpret_cast<const unsigned long long*>(&hs[w * 4 + r][j]);
            fma2(acc[r][0], hp, wp01);
            fma2(acc[r][1], hp, wp23);
        }
    }
#pragma unroll
    for (int r = 0; r < 4; r++) {
        float4 o;
        unpack2(acc[r][0], o.x, o.y);
        unpack2(acc[r][1], o.z, o.w);
        size_t base = ((size_t)blockIdx.y * RR + (w * 4 + r)) * DD + dbt + lane * 4;
        *reinterpret_cast<float4*>(&g_opart[base]) = o;
    }
}

// ---------------- kernel 7: reduce partials, add b2, scale, write (float4) ----------------
// grid (32 rows, 4 chunks of 256 cols), 256 threads.
// Thread t: float4 col (t&63), split-group (t>>6) sums 16 splits; smem combine.
__global__ void final_kernel(const float* __restrict__ b2,
                             float* __restrict__ out) {
    __shared__ float4 part[256];
    int r = blockIdx.x;
    int cbase = blockIdx.y * 256;        // col base (floats)
    int t = threadIdx.x;
    int c4 = t & 63;                     // float4 col within chunk
    int sg = t >> 6;                     // split group 0..3

    float4 v = make_float4(0.f, 0.f, 0.f, 0.f);
#pragma unroll
    for (int s = 0; s < 16; s++) {
        int sp = sg * 16 + s;
        float4 p = *reinterpret_cast<const float4*>(
            &g_opart[((size_t)sp * RR + r) * DD + cbase + c4 * 4]);
        v.x += p.x; v.y += p.y; v.z += p.z; v.w += p.w;
    }
    part[t] = v;
    __syncthreads();
    if (t < 64) {
        float4 a = part[t], b = part[t + 64], c = part[t + 128], d = part[t + 192];
        float4 bias = *reinterpret_cast<const float4*>(&b2[cbase + t * 4]);
        float gs = g_gs[r];
        float4 o;
        o.x = gs * (a.x + b.x + c.x + d.x + bias.x);
        o.y = gs * (a.y + b.y + c.y + d.y + bias.y);
        o.z = gs * (a.z + b.z + c.z + d.z + bias.z);
        o.w = gs * (a.w + b.w + c.w + d.w + bias.w);
        *reinterpret_cast<float4*>(&out[row_x_off(r) + cbase + t * 4]) = o;
    }
}

// ---------------- launch ----------------
extern "C" void kernel_launch(void* const* d_in, const int* in_sizes, int n_in,
                              void* d_out, int out_size) {
    const float* x      = (const float*)d_in[0];
    const float* w_gate = (const float*)d_in[1];
    const float* b_gate = (const float*)d_in[2];
    const float* w1     = (const float*)d_in[3];
    const float* b1     = (const float*)d_in[4];
    const float* w2     = (const float*)d_in[5];
    const float* b2     = (const float*)d_in[6];
    float* out = (float*)d_out;

    cudaMemsetAsync(d_out, 0, (size_t)OUT_ELEMS * sizeof(float));

    init_kernel<<<32, 256>>>(w_gate);
    gate_kernel<<<256, 256>>>(x, b_gate);
    score_loss_kernel<<<1, 32>>>(out);
    stage1_kernel<<<dim3(32, S1_SPLITS), 256>>>(x, w1);
    gelu_kernel<<<128, 256>>>(b1);
    stage2_kernel<<<dim3(8, S2_SPLITS), 256>>>(w2);
    final_kernel<<<dim3(32, 4), 256>>>(b2, out);
}

// round 8
// speedup vs baseline: 2.7820x; 1.0007x over previous
#include <cuda_runtime.h>
#include <math.h>

#define BB 4
#define NN 512
#define DD 1024
#define EE 8
#define HH 4096
#define RR 32            // candidate rows: (b in 0..3) x (n in 0..7)
#define OUT_ELEMS (BB*NN*DD)

#define S1_SPLITS 16     // stage1 d-splits (64 d each, combined in-block)
#define S2_SPLITS 64     // stage2 j-splits (64 j each, combined in-block)

// ---------------- device scratch ----------------
__device__ float g_wt[EE*DD];                // transposed gate weights [e][d]
__device__ int   g_flag[RR];
__device__ float g_gate0[RR];
__device__ float g_gs[RR];
__device__ float g_hpart[S1_SPLITS*RR*HH];   // 8 MB
__device__ float g_h[RR*HH];
__device__ float g_opart[S2_SPLITS*RR*DD];   // 8 MB

// ---------------- packed fp32x2 helpers ----------------
__device__ __forceinline__ void fma2(unsigned long long& d,
                                     unsigned long long a,
                                     unsigned long long b) {
    asm("fma.rn.f32x2 %0, %1, %2, %0;" : "+l"(d) : "l"(a), "l"(b));
}
__device__ __forceinline__ unsigned long long pack2(float lo, float hi) {
    unsigned long long r;
    asm("mov.b64 %0, {%1, %2};" : "=l"(r) : "f"(lo), "f"(hi));
    return r;
}
__device__ __forceinline__ void unpack2(unsigned long long v, float& lo, float& hi) {
    asm("mov.b64 {%0, %1}, %2;" : "=f"(lo), "=f"(hi) : "l"(v));
}

__device__ __forceinline__ int row_x_off(int r) {
    return ((r >> 3) * NN + (r & 7)) * DD;
}

// ---------------- kernel 1: init flags + transpose w_gate ----------------
__global__ void init_kernel(const float* __restrict__ w_gate) {
    int idx = blockIdx.x * blockDim.x + threadIdx.x;
    if (idx < EE * DD) {
        int e = idx & 7, d = idx >> 3;
        g_wt[e * DD + d] = w_gate[idx];
    }
    if (idx < RR) g_flag[idx] = 0;
}

// ---------------- kernel 2: gate logits, argmax, p(e=0) for n<8 ----------------
// 256 blocks x 256 threads; one token per warp; float4 loads
__global__ void gate_kernel(const float* __restrict__ x,
                            const float* __restrict__ b_gate) {
    int tok  = (blockIdx.x * blockDim.x + threadIdx.x) >> 5;
    int lane = threadIdx.x & 31;

    float acc[8];
#pragma unroll
    for (int e = 0; e < 8; e++) acc[e] = 0.f;

    const float4* xp = reinterpret_cast<const float4*>(x + (size_t)tok * DD) + lane;
#pragma unroll
    for (int i = 0; i < 8; i++) {
        int d4 = i * 32 + lane;
        float4 xv = xp[i * 32];
#pragma unroll
        for (int e = 0; e < 8; e++) {
            float4 wv = *reinterpret_cast<const float4*>(&g_wt[e * DD + d4 * 4]);
            acc[e] += xv.x * wv.x + xv.y * wv.y + xv.z * wv.z + xv.w * wv.w;
        }
    }
#pragma unroll
    for (int e = 0; e < 8; e++)
#pragma unroll
        for (int off = 16; off > 0; off >>= 1)
            acc[e] += __shfl_xor_sync(0xffffffffu, acc[e], off);

    if (lane == 0) {
        float l[8];
#pragma unroll
        for (int e = 0; e < 8; e++) l[e] = acc[e] + b_gate[e];
        int am = 0; float mx = l[0];
#pragma unroll
        for (int e = 1; e < 8; e++) if (l[e] > mx) { mx = l[e]; am = e; }
        int b = tok >> 9;
        int n = tok & 511;
        g_flag[b * 8 + am] = 1;          // benign race: writers all store 1
        if (n < 8) {
            float s = 0.f, p0 = 0.f;
#pragma unroll
            for (int e = 0; e < 8; e++) {
                float t = expf(l[e] - mx);
                s += t;
                if (e == 0) p0 = t;
            }
            g_gate0[b * 8 + n] = p0 / s;
        }
    }
}

// ---------------- kernel 3: gate scores + aux loss (1 warp) ----------------
__global__ void score_loss_kernel(float* __restrict__ out) {
    int i = threadIdx.x;                 // b = i>>3, n = i&7
    float m = g_flag[i] ? g_gate0[i] : 0.f;
    float s = m;
    s += __shfl_xor_sync(0xffffffffu, s, 8);
    s += __shfl_xor_sync(0xffffffffu, s, 16);
    float gs = m / (s + 1e-6f) * 4.0f;   // capacity = 4
    g_gs[i] = gs;

    float imp = gs;
    imp += __shfl_xor_sync(0xffffffffu, imp, 8);
    imp += __shfl_xor_sync(0xffffffffu, imp, 16);
    float ld = (float)g_flag[i];
    ld += __shfl_xor_sync(0xffffffffu, ld, 8);
    ld += __shfl_xor_sync(0xffffffffu, ld, 16);

    float s1 = (i < 8) ? imp       : 0.f;
    float s2 = (i < 8) ? imp * imp : 0.f;
    float s3 = (i < 8) ? ld        : 0.f;
    float s4 = (i < 8) ? ld * ld   : 0.f;
#pragma unroll
    for (int off = 16; off > 0; off >>= 1) {
        s1 += __shfl_xor_sync(0xffffffffu, s1, off);
        s2 += __shfl_xor_sync(0xffffffffu, s2, off);
        s3 += __shfl_xor_sync(0xffffffffu, s3, off);
        s4 += __shfl_xor_sync(0xffffffffu, s4, off);
    }
    if (i == 0) {
        const float NEL = (float)(NN * EE);
        float m1 = s1 / NEL;
        float v1 = (s2 - s1 * s1 / NEL) / (NEL - 1.f);
        float m2 = s3 / NEL;
        float v2 = (s4 - s3 * s3 / NEL) / (NEL - 1.f);
        out[OUT_ELEMS] = v1 / (m1 * m1 + 1e-10f) + v2 / (m2 * m2 + 1e-10f);
    }
}

// ---------------- kernel 4: stage1 GEMM  h_pre = x[32,1024] @ w1[0] ----------------
// grid (32 j-tiles of 128 cols, 16 d-blocks of 64), 256 threads (8 warps).
// Warp-group split: warps 0-3 own d[0:32], warps 4-7 own d[32:64].
// Each warp: 8 rows x 128 cols -> 16 FFMA2 per LDG.128. In-block smem combine.
__global__ void stage1_kernel(const float* __restrict__ x,
                              const float* __restrict__ w1) {
    __shared__ float2 xs[RR][64];        // splatted x tile, 16 KB
    __shared__ float comb[RR][128];      // combine buffer, 16 KB
    int t = threadIdx.x;
    int jb = blockIdx.x * 128;
    int db = blockIdx.y * 64;

#pragma unroll
    for (int q = 0; q < 8; q++) {
        int idx = t + 256 * q;           // 2048 entries
        int row = idx >> 6, dd = idx & 63;
        float v = x[row_x_off(row) + db + dd];
        xs[row][dd] = make_float2(v, v);
    }
    __syncthreads();

    int lane = t & 31, w = t >> 5;
    int wr = w & 3, dgrp = w >> 2;
    int rbase = wr * 8;
    int d0 = dgrp * 32;

    unsigned long long acc[8][2];        // [row][colpair]
#pragma unroll
    for (int r = 0; r < 8; r++) { acc[r][0] = 0ULL; acc[r][1] = 0ULL; }

    const float* wbase = w1 + (size_t)(db + d0) * HH + jb + lane * 4;
#pragma unroll 8
    for (int d = 0; d < 32; d++) {
        float4 wv = *reinterpret_cast<const float4*>(wbase + (size_t)d * HH);
        unsigned long long wp01 = pack2(wv.x, wv.y);
        unsigned long long wp23 = pack2(wv.z, wv.w);
#pragma unroll
        for (int r = 0; r < 8; r++) {
            unsigned long long xp = *reinterpret_cast<const unsigned long long*>(
                &xs[rbase + r][d0 + d]);
            fma2(acc[r][0], xp, wp01);
            fma2(acc[r][1], xp, wp23);
        }
    }

    if (dgrp == 1) {
#pragma unroll
        for (int r = 0; r < 8; r++) {
            float4 o;
            unpack2(acc[r][0], o.x, o.y);
            unpack2(acc[r][1], o.z, o.w);
            *reinterpret_cast<float4*>(&comb[rbase + r][lane * 4]) = o;
        }
    }
    __syncthreads();
    if (dgrp == 0) {
#pragma unroll
        for (int r = 0; r < 8; r++) {
            float4 o;
            unpack2(acc[r][0], o.x, o.y);
            unpack2(acc[r][1], o.z, o.w);
            float4 c = *reinterpret_cast<const float4*>(&comb[rbase + r][lane * 4]);
            o.x += c.x; o.y += c.y; o.z += c.z; o.w += c.w;
            size_t base = ((size_t)blockIdx.y * RR + rbase + r) * HH + jb + lane * 4;
            *reinterpret_cast<float4*>(&g_hpart[base]) = o;
        }
    }
}

// ---------------- kernel 5: split-K reduce + bias + exact GELU (float4) ----------------
__global__ void gelu_kernel(const float* __restrict__ b1) {
    int f4 = blockIdx.x * blockDim.x + threadIdx.x;     // 0..32767
    int h = (f4 * 4) & 4095;
    float4 v = *reinterpret_cast<const float4*>(&b1[h]);
#pragma unroll
    for (int s = 0; s < S1_SPLITS; s++) {
        float4 p = *reinterpret_cast<const float4*>(&g_hpart[(size_t)s * (RR * HH) + f4 * 4]);
        v.x += p.x; v.y += p.y; v.z += p.z; v.w += p.w;
    }
    const float k = 0.70710678118654752440f;
    v.x = 0.5f * v.x * (1.0f + erff(v.x * k));
    v.y = 0.5f * v.y * (1.0f + erff(v.y * k));
    v.z = 0.5f * v.z * (1.0f + erff(v.z * k));
    v.w = 0.5f * v.w * (1.0f + erff(v.w * k));
    *reinterpret_cast<float4*>(&g_h[f4 * 4]) = v;
}

// ---------------- kernel 6: stage2 GEMM  o_pre = h[32,4096] @ w2[0] ----------------
// grid (8 d-tiles of 128 cols, 64 j-blocks of 64), 256 threads (8 warps).
// Same warp-group structure as stage1: warps 0-3 j[0:32], warps 4-7 j[32:64].
__global__ void stage2_kernel(const float* __restrict__ w2) {
    __shared__ float2 hs[RR][64];        // splatted h tile, 16 KB
    __shared__ float comb[RR][128];      // 16 KB
    int t = threadIdx.x;
    int dbt = blockIdx.x * 128;
    int jb  = blockIdx.y * 64;

#pragma unroll
    for (int q = 0; q < 8; q++) {
        int idx = t + 256 * q;
        int row = idx >> 6, jj = idx & 63;
        float v = g_h[row * HH + jb + jj];
        hs[row][jj] = make_float2(v, v);
    }
    __syncthreads();

    int lane = t & 31, w = t >> 5;
    int wr = w & 3, jgrp = w >> 2;
    int rbase = wr * 8;
    int j0 = jgrp * 32;

    unsigned long long acc[8][2];
#pragma unroll
    for (int r = 0; r < 8; r++) { acc[r][0] = 0ULL; acc[r][1] = 0ULL; }

    const float* wbase = w2 + (size_t)(jb + j0) * DD + dbt + lane * 4;
#pragma unroll 8
    for (int j = 0; j < 32; j++) {
        float4 wv = *reinterpret_cast<const float4*>(wbase + (size_t)j * DD);
        unsigned long long wp01 = pack2(wv.x, wv.y);
        unsigned long long wp23 = pack2(wv.z, wv.w);
#pragma unroll
        for (int r = 0; r < 8; r++) {
            unsigned long long hp = *reinterpret_cast<const unsigned long long*>(
                &hs[rbase + r][j0 + j]);
            fma2(acc[r][0], hp, wp01);
            fma2(acc[r][1], hp, wp23);
        }
    }

    if (jgrp == 1) {
#pragma unroll
        for (int r = 0; r < 8; r++) {
            float4 o;
            unpack2(acc[r][0], o.x, o.y);
            unpack2(acc[r][1], o.z, o.w);
            *reinterpret_cast<float4*>(&comb[rbase + r][lane * 4]) = o;
        }
    }
    __syncthreads();
    if (jgrp == 0) {
#pragma unroll
        for (int r = 0; r < 8; r++) {
            float4 o;
            unpack2(acc[r][0], o.x, o.y);
            unpack2(acc[r][1], o.z, o.w);
            float4 c = *reinterpret_cast<const float4*>(&comb[rbase + r][lane * 4]);
            o.x += c.x; o.y += c.y; o.z += c.z; o.w += c.w;
            size_t base = ((size_t)blockIdx.y * RR + rbase + r) * DD + dbt + lane * 4;
            *reinterpret_cast<float4*>(&g_opart[base]) = o;
        }
    }
}

// ---------------- kernel 7: reduce partials, add b2, scale, write (float4) ----------------
// grid (32 rows, 4 chunks of 256 cols), 256 threads.
__global__ void final_kernel(const float* __restrict__ b2,
                             float* __restrict__ out) {
    __shared__ float4 part[256];
    int r = blockIdx.x;
    int cbase = blockIdx.y * 256;
    int t = threadIdx.x;
    int c4 = t & 63;
    int sg = t >> 6;

    float4 v = make_float4(0.f, 0.f, 0.f, 0.f);
#pragma unroll
    for (int s = 0; s < 16; s++) {
        int sp = sg * 16 + s;
        float4 p = *reinterpret_cast<const float4*>(
            &g_opart[((size_t)sp * RR + r) * DD + cbase + c4 * 4]);
        v.x += p.x; v.y += p.y; v.z += p.z; v.w += p.w;
    }
    part[t] = v;
    __syncthreads();
    if (t < 64) {
        float4 a = part[t], b = part[t + 64], c = part[t + 128], d = part[t + 192];
        float4 bias = *reinterpret_cast<const float4*>(&b2[cbase + t * 4]);
        float gs = g_gs[r];
        float4 o;
        o.x = gs * (a.x + b.x + c.x + d.x + bias.x);
        o.y = gs * (a.y + b.y + c.y + d.y + bias.y);
        o.z = gs * (a.z + b.z + c.z + d.z + bias.z);
        o.w = gs * (a.w + b.w + c.w + d.w + bias.w);
        *reinterpret_cast<float4*>(&out[row_x_off(r) + cbase + t * 4]) = o;
    }
}

// ---------------- launch ----------------
extern "C" void kernel_launch(void* const* d_in, const int* in_sizes, int n_in,
                              void* d_out, int out_size) {
    const float* x      = (const float*)d_in[0];
    const float* w_gate = (const float*)d_in[1];
    const float* b_gate = (const float*)d_in[2];
    const float* w1     = (const float*)d_in[3];
    const float* b1     = (const float*)d_in[4];
    const float* w2     = (const float*)d_in[5];
    const float* b2     = (const float*)d_in[6];
    float* out = (float*)d_out;

    cudaMemsetAsync(d_out, 0, (size_t)OUT_ELEMS * sizeof(float));

    init_kernel<<<32, 256>>>(w_gate);
    gate_kernel<<<256, 256>>>(x, b_gate);
    score_loss_kernel<<<1, 32>>>(out);
    stage1_kernel<<<dim3(32, S1_SPLITS), 256>>>(x, w1);
    gelu_kernel<<<128, 256>>>(b1);
    stage2_kernel<<<dim3(8, S2_SPLITS), 256>>>(w2);
    final_kernel<<<dim3(32, 4), 256>>>(b2, out);
}